// round 7
// baseline (speedup 1.0000x reference)
#include <cuda_runtime.h>
#include <cstdint>

#define D 128            // DH == DX == 128
#define MAX_M 4096
#define MAX_N 262144

#define PROJ_BLOCKS 256      // 16 rows each -> 4096 rows
#define PROJ_ROWS   16

#define CHUNK  8             // nodes per bulk copy (8 * 512B = 4KB)
#define STAGES 4             // per-warp ring depth (16KB)
#define RANGE  224           // nodes per warp-range (28 chunks)
#define MAX_RANGES ((MAX_N + RANGE - 1) / RANGE + 1)

// Scratch (no allocations allowed)
__device__ float  g_proj[MAX_M * D];
__device__ int    g_offsets[MAX_M + 1];
__device__ float  g_part_m[MAX_RANGES * 2];
__device__ float  g_part_z[MAX_RANGES * 2];
__device__ float4 g_part_acc[MAX_RANGES * 2 * 32];

// ---------------------------------------------------------------------------
// PTX helpers: mbarrier + cp.async.bulk
// ---------------------------------------------------------------------------
__device__ __forceinline__ uint32_t smem_u32(const void* p) {
    return (uint32_t)__cvta_generic_to_shared(p);
}
__device__ __forceinline__ void mbar_init(uint32_t bar, uint32_t cnt) {
    asm volatile("mbarrier.init.shared.b64 [%0], %1;" :: "r"(bar), "r"(cnt) : "memory");
}
__device__ __forceinline__ void mbar_expect(uint32_t bar, uint32_t bytes) {
    asm volatile("mbarrier.arrive.expect_tx.shared.b64 _, [%0], %1;"
                 :: "r"(bar), "r"(bytes) : "memory");
}
__device__ __forceinline__ void bulk_ld(uint32_t dst, const void* src,
                                        uint32_t bytes, uint32_t bar) {
    asm volatile(
        "cp.async.bulk.shared::cta.global.mbarrier::complete_tx::bytes [%0], [%1], %2, [%3];"
        :: "r"(dst), "l"(src), "r"(bytes), "r"(bar) : "memory");
}
__device__ __forceinline__ void mbar_wait(uint32_t bar, uint32_t phase) {
    uint32_t done;
    asm volatile(
        "{\n\t.reg .pred p;\n\t"
        "mbarrier.try_wait.parity.acquire.cta.shared::cta.b64 p, [%1], %2;\n\t"
        "selp.b32 %0, 1, 0, p;\n\t}"
        : "=r"(done) : "r"(bar), "r"(phase) : "memory");
    if (!done) {
        asm volatile(
            "{\n\t.reg .pred P1;\n\t"
            "WAIT_LOOP_%=:\n\t"
            "mbarrier.try_wait.parity.acquire.cta.shared::cta.b64 P1, [%0], %1, 0x989680;\n\t"
            "@P1 bra.uni WAIT_DONE_%=;\n\t"
            "bra.uni WAIT_LOOP_%=;\n\t"
            "WAIT_DONE_%=:\n\t}"
            :: "r"(bar), "r"(phase) : "memory");
    }
}

// ---------------------------------------------------------------------------
// Kernel A (fused): proj = h @ a  +  segment offsets (unchanged, works)
// ---------------------------------------------------------------------------
__global__ __launch_bounds__(256) void pre_kernel(const float* __restrict__ h,
                                                  const float* __restrict__ a,
                                                  const int* __restrict__ seg,
                                                  int n, int m) {
    __shared__ float a_sh[64 * D];
    __shared__ float h_sh[PROJ_ROWS * D];

    int tid = threadIdx.x;

    if (blockIdx.x < PROJ_BLOCKS) {
        int cg = tid & 31;
        int rg = tid >> 5;
        int rowBase = blockIdx.x * PROJ_ROWS;

        const float4* h4 = (const float4*)h;
        const float4* a4 = (const float4*)a;
        float4* h_sh4 = (float4*)h_sh;
        float4* a_sh4 = (float4*)a_sh;

        for (int idx = tid; idx < PROJ_ROWS * (D / 4); idx += 256)
            h_sh4[idx] = h4[rowBase * (D / 4) + idx];

        float acc[2][4];
#pragma unroll
        for (int r = 0; r < 2; r++)
            acc[r][0] = acc[r][1] = acc[r][2] = acc[r][3] = 0.f;

        for (int half = 0; half < 2; half++) {
            __syncthreads();
            for (int idx = tid; idx < 64 * (D / 4); idx += 256)
                a_sh4[idx] = a4[half * 64 * (D / 4) + idx];
            __syncthreads();

#pragma unroll 8
            for (int k2 = 0; k2 < 64; k2++) {
                float4 av = *(const float4*)&a_sh[k2 * D + cg * 4];
                int k = half * 64 + k2;
#pragma unroll
                for (int r = 0; r < 2; r++) {
                    float hv = h_sh[(rg * 2 + r) * D + k];
                    acc[r][0] = fmaf(hv, av.x, acc[r][0]);
                    acc[r][1] = fmaf(hv, av.y, acc[r][1]);
                    acc[r][2] = fmaf(hv, av.z, acc[r][2]);
                    acc[r][3] = fmaf(hv, av.w, acc[r][3]);
                }
            }
        }

        float4* p4 = (float4*)g_proj;
#pragma unroll
        for (int r = 0; r < 2; r++) {
            int row = rowBase + rg * 2 + r;
            p4[row * (D / 4) + cg] =
                make_float4(acc[r][0], acc[r][1], acc[r][2], acc[r][3]);
        }
    } else {
        int t = (blockIdx.x - PROJ_BLOCKS) * 256 + tid;
        int base = t * 4;
        if (base >= n) return;
        int4 v = ((const int4*)seg)[t];
        int prev = (base == 0) ? -1 : __ldg(&seg[base - 1]);

        int ids[4] = {v.x, v.y, v.z, v.w};
#pragma unroll
        for (int k = 0; k < 4; k++) {
            int s = ids[k];
            for (int g = prev + 1; g <= s; ++g) g_offsets[g] = base + k;
            prev = s;
        }
        if (base + 4 >= n) {
            for (int g = prev + 1; g <= m; ++g) g_offsets[g] = n;
        }
    }
}

// ---------------------------------------------------------------------------
// Flash helpers
// ---------------------------------------------------------------------------
__device__ __forceinline__ float warp_dot(float4 v, float4 p) {
    float d = fmaf(v.x, p.x, fmaf(v.y, p.y, fmaf(v.z, p.z, v.w * p.w)));
    d += __shfl_xor_sync(0xffffffffu, d, 16);
    d += __shfl_xor_sync(0xffffffffu, d, 8);
    d += __shfl_xor_sync(0xffffffffu, d, 4);
    d += __shfl_xor_sync(0xffffffffu, d, 2);
    d += __shfl_xor_sync(0xffffffffu, d, 1);
    return d;
}

__device__ __forceinline__ void flash4(const float4* __restrict__ b, float4 p,
                                       float& m_w, float& z_w, float4& acc) {
    float4 v0 = b[0];
    float4 v1 = b[32];
    float4 v2 = b[64];
    float4 v3 = b[96];
    float d0 = warp_dot(v0, p);
    float d1 = warp_dot(v1, p);
    float d2 = warp_dot(v2, p);
    float d3 = warp_dot(v3, p);
    float m_new = fmaxf(fmaxf(m_w, fmaxf(d0, d1)), fmaxf(d2, d3));
    float c  = __expf(m_w - m_new);
    float e0 = __expf(d0 - m_new);
    float e1 = __expf(d1 - m_new);
    float e2 = __expf(d2 - m_new);
    float e3 = __expf(d3 - m_new);
    z_w   = fmaf(z_w, c, (e0 + e1) + (e2 + e3));
    acc.x = fmaf(acc.x, c, fmaf(e0, v0.x, fmaf(e1, v1.x, fmaf(e2, v2.x, e3 * v3.x))));
    acc.y = fmaf(acc.y, c, fmaf(e0, v0.y, fmaf(e1, v1.y, fmaf(e2, v2.y, e3 * v3.y))));
    acc.z = fmaf(acc.z, c, fmaf(e0, v0.z, fmaf(e1, v1.z, fmaf(e2, v2.z, e3 * v3.z))));
    acc.w = fmaf(acc.w, c, fmaf(e0, v0.w, fmaf(e1, v1.w, fmaf(e2, v2.w, e3 * v3.w))));
    m_w = m_new;
}

__device__ __forceinline__ void flash1(float4 v, float4 p,
                                       float& m_w, float& z_w, float4& acc) {
    float d  = warp_dot(v, p);
    float m_new = fmaxf(m_w, d);
    float c = __expf(m_w - m_new);
    float e = __expf(d - m_new);
    z_w   = fmaf(z_w, c, e);
    acc.x = fmaf(acc.x, c, e * v.x);
    acc.y = fmaf(acc.y, c, e * v.y);
    acc.z = fmaf(acc.z, c, e * v.z);
    acc.w = fmaf(acc.w, c, e * v.w);
    m_w = m_new;
}

// Close the current graph: direct output if fully interior, else scratch slot.
__device__ __forceinline__ void close_graph(float4* out4, int g, bool direct,
                                            int slot, float mw, float zw,
                                            float4 acc, int lane) {
    if (direct) {
        float inv = 1.f / zw;
        out4[g * 32 + lane] =
            make_float4(acc.x * inv, acc.y * inv, acc.z * inv, acc.w * inv);
    } else {
        if (lane == 0) { g_part_m[slot] = mw; g_part_z[slot] = zw; }
        g_part_acc[slot * 32 + lane] = acc;
    }
}

// ---------------------------------------------------------------------------
// Kernel B: NODE-RANGE streaming online softmax.
// Each warp owns a fixed contiguous RANGE-node slice of x and streams it
// through a STAGES-deep bulk-async smem ring — one pipeline fill per 28
// chunks instead of one per graph. Graph boundaries handled in the consumer;
// boundary-cut graphs emit flash partials to scratch (combined in pass C).
// ---------------------------------------------------------------------------
__global__ __launch_bounds__(128) void attn_kernel(const float* __restrict__ x,
                                                   const int* __restrict__ seg,
                                                   float* __restrict__ out,
                                                   int n, int m) {
    extern __shared__ unsigned char dyn[];
    float4*   bufs = (float4*)dyn;                               // [4][STAGES][CHUNK*32]
    uint64_t* bars = (uint64_t*)(dyn + 4 * STAGES * CHUNK * 512);

    int tid  = threadIdx.x;
    int lane = tid & 31;
    int w    = tid >> 5;

    float4*   buf = bufs + w * STAGES * (CHUNK * 32);
    uint64_t* bar = bars + w * STAGES;

    if (lane == 0)
        for (int s = 0; s < STAGES; s++) mbar_init(smem_u32(&bar[s]), 1);
    __syncthreads();

    int rid = blockIdx.x * 4 + w;      // range id
    int r0  = rid * RANGE;
    if (r0 >= n) return;
    int r1  = min(r0 + RANGE, n);
    int len = r1 - r0;
    int nch = (len + CHUNK - 1) / CHUNK;

    const float4* x4   = (const float4*)x;
    const float4* pr4  = (const float4*)g_proj;
    float4*       out4 = (float4*)out;

    // ---- prologue: fill the ring ----
    if (lane == 0) {
        int npre = nch < STAGES ? nch : STAGES;
        for (int k = 0; k < npre; k++) {
            int rem   = len - k * CHUNK;
            int bytes = (rem < CHUNK ? rem : CHUNK) * 512;
            uint32_t b = smem_u32(&bar[k]);
            mbar_expect(b, (uint32_t)bytes);
            bulk_ld(smem_u32(buf + k * (CHUNK * 32)),
                    x4 + (size_t)(r0 + k * CHUNK) * 32, (uint32_t)bytes, b);
        }
    }

    // ---- segment state ----
    int g      = __ldg(&seg[r0]);          // graph containing first node
    int gFirst = g;
    int sg     = g_offsets[g];
    int eg     = g_offsets[g + 1];
    bool startedIn = (sg == r0);           // sg <= r0 always

    const float NEG_INF = -3.402823466e38f;
    float4 p   = pr4[g * 32 + lane];
    float  mw  = NEG_INF;
    float  zw  = 0.f;
    float4 acc = make_float4(0.f, 0.f, 0.f, 0.f);

    // ---- stream chunks ----
    for (int c = 0; c < nch; c++) {
        int st = c & (STAGES - 1);
        mbar_wait(smem_u32(&bar[st]), (c >> 2) & 1);
        const float4* bs = buf + st * (CHUNK * 32);
        int cbeg = r0 + c * CHUNK;
        int cend = cbeg + CHUNK < r1 ? cbeg + CHUNK : r1;

        int i = cbeg;
        while (i < cend) {
            if (i >= eg) {
                // close current graph at its true end
                close_graph(out4, g, startedIn,
                            rid * 2 + (g == gFirst ? 0 : 1), mw, zw, acc, lane);
                do { ++g; eg = g_offsets[g + 1]; } while (eg <= i);
                startedIn = true;
                p  = pr4[g * 32 + lane];
                mw = NEG_INF; zw = 0.f;
                acc = make_float4(0.f, 0.f, 0.f, 0.f);
            }
            int stop = cend < eg ? cend : eg;
            const float4* bp = bs + (i - cbeg) * 32 + lane;
            if (stop - i == 8) {
                flash4(bp,       p, mw, zw, acc);
                flash4(bp + 128, p, mw, zw, acc);
            } else {
                int cntN = stop - i;
                for (int k = 0; k < cntN; k++)
                    flash1(bp[k * 32], p, mw, zw, acc);
            }
            i = stop;
        }

        __syncwarp();
        // refill this stage with chunk c + STAGES
        if (lane == 0 && c + STAGES < nch) {
            int k     = c + STAGES;
            int rem   = len - k * CHUNK;
            int bytes = (rem < CHUNK ? rem : CHUNK) * 512;
            uint32_t b = smem_u32(&bar[st]);
            mbar_expect(b, (uint32_t)bytes);
            bulk_ld(smem_u32(buf + st * (CHUNK * 32)),
                    x4 + (size_t)(r0 + k * CHUNK) * 32, (uint32_t)bytes, b);
        }
    }

    // ---- final close at range end ----
    {
        bool trueEnd = (eg == r1);
        close_graph(out4, g, trueEnd && startedIn,
                    rid * 2 + (g == gFirst ? 0 : 1), mw, zw, acc, lane);
    }
}

// ---------------------------------------------------------------------------
// Kernel C: combine boundary partials. One warp per graph.
// Interior non-empty graphs (single range) were written by pass B; empty
// graphs get zeros; spanning graphs flash-combine their per-range partials.
// ---------------------------------------------------------------------------
__global__ __launch_bounds__(256) void combine_kernel(float* __restrict__ out,
                                                      int m) {
    int gw   = (blockIdx.x * blockDim.x + threadIdx.x) >> 5;
    int lane = threadIdx.x & 31;
    if (gw >= m) return;

    int s = g_offsets[gw];
    int e = g_offsets[gw + 1];
    float4* out4 = (float4*)out;

    if (s >= e) {                               // empty graph
        out4[gw * 32 + lane] = make_float4(0.f, 0.f, 0.f, 0.f);
        return;
    }
    int i0 = s / RANGE;
    int i1 = (e - 1) / RANGE;
    if (i0 == i1) return;                       // interior: pass B wrote it

    const float NEG_INF = -3.402823466e38f;
    float  M = NEG_INF, Z = 0.f;
    float4 A = make_float4(0.f, 0.f, 0.f, 0.f);
    for (int j = i0; j <= i1; j++) {
        int slot = 2 * j + ((j == i0 && (s % RANGE != 0)) ? 1 : 0);
        float  mj = g_part_m[slot];
        float  zj = g_part_z[slot];
        float4 aj = g_part_acc[slot * 32 + lane];
        float nM = fmaxf(M, mj);
        float fo = __expf(M - nM);
        float fn = __expf(mj - nM);
        Z   = fmaf(Z, fo, zj * fn);
        A.x = fmaf(A.x, fo, aj.x * fn);
        A.y = fmaf(A.y, fo, aj.y * fn);
        A.z = fmaf(A.z, fo, aj.z * fn);
        A.w = fmaf(A.w, fo, aj.w * fn);
        M = nM;
    }
    float inv = 1.f / Z;
    out4[gw * 32 + lane] = make_float4(A.x * inv, A.y * inv, A.z * inv, A.w * inv);
}

// ---------------------------------------------------------------------------
// Launch: inputs per metadata order: h (M*128 f32), x (N*128 f32),
// a (128*128 f32), segment_ids (N int32). Output: M*128 f32.
// ---------------------------------------------------------------------------
extern "C" void kernel_launch(void* const* d_in, const int* in_sizes, int n_in,
                              void* d_out, int out_size) {
    const float* h   = (const float*)d_in[0];
    const float* x   = (const float*)d_in[1];
    const float* a   = (const float*)d_in[2];
    const int*   seg = (const int*)d_in[3];
    float* out = (float*)d_out;

    int m = in_sizes[0] / D;   // 4096
    int n = in_sizes[3];       // 262144

    int n4 = (n + 3) / 4;
    int off_blocks = (n4 + 255) / 256;
    pre_kernel<<<PROJ_BLOCKS + off_blocks, 256>>>(h, a, seg, n, m);

    int smem_bytes = 4 * STAGES * CHUNK * 512 + 4 * STAGES * 8;   // 65664
    static bool attr_set = false;
    if (!attr_set) {
        cudaFuncSetAttribute(attn_kernel,
                             cudaFuncAttributeMaxDynamicSharedMemorySize,
                             smem_bytes);
        attr_set = true;
    }
    int nranges = (n + RANGE - 1) / RANGE;
    int ablocks = (nranges + 3) / 4;
    attn_kernel<<<ablocks, 128, smem_bytes>>>(x, seg, out, n, m);

    combine_kernel<<<(m * 32 + 255) / 256, 256>>>(out, m);
}

// round 8
// speedup vs baseline: 1.0364x; 1.0364x over previous
#include <cuda_runtime.h>
#include <cstdint>

#define D 128            // DH == DX == 128
#define MAX_M 4096
#define MAX_N 262144

#define PROJ_BLOCKS 256      // 8 warps x 2 rows = 16 rows/block -> 4096 rows

#define CHUNK  8             // nodes per bulk copy (8 * 512B = 4KB)
#define STAGES 2

// Scratch (no allocations allowed): proj matrix + segment offsets
__device__ float g_proj[MAX_M * D];
__device__ int   g_offsets[MAX_M + 1];

// ---------------------------------------------------------------------------
// PTX helpers: mbarrier + cp.async.bulk (async-proxy global->shared stream)
// ---------------------------------------------------------------------------
__device__ __forceinline__ uint32_t smem_u32(const void* p) {
    return (uint32_t)__cvta_generic_to_shared(p);
}
__device__ __forceinline__ void mbar_init(uint32_t bar, uint32_t cnt) {
    asm volatile("mbarrier.init.shared.b64 [%0], %1;" :: "r"(bar), "r"(cnt) : "memory");
}
__device__ __forceinline__ void mbar_expect(uint32_t bar, uint32_t bytes) {
    asm volatile("mbarrier.arrive.expect_tx.shared.b64 _, [%0], %1;"
                 :: "r"(bar), "r"(bytes) : "memory");
}
__device__ __forceinline__ void bulk_ld(uint32_t dst, const void* src,
                                        uint32_t bytes, uint32_t bar) {
    asm volatile(
        "cp.async.bulk.shared::cta.global.mbarrier::complete_tx::bytes [%0], [%1], %2, [%3];"
        :: "r"(dst), "l"(src), "r"(bytes), "r"(bar) : "memory");
}
__device__ __forceinline__ void mbar_wait(uint32_t bar, uint32_t phase) {
    uint32_t done;
    asm volatile(
        "{\n\t.reg .pred p;\n\t"
        "mbarrier.try_wait.parity.acquire.cta.shared::cta.b64 p, [%1], %2;\n\t"
        "selp.b32 %0, 1, 0, p;\n\t}"
        : "=r"(done) : "r"(bar), "r"(phase) : "memory");
    if (!done) {
        asm volatile(
            "{\n\t.reg .pred P1;\n\t"
            "WAIT_LOOP_%=:\n\t"
            "mbarrier.try_wait.parity.acquire.cta.shared::cta.b64 P1, [%0], %1, 0x989680;\n\t"
            "@P1 bra.uni WAIT_DONE_%=;\n\t"
            "bra.uni WAIT_LOOP_%=;\n\t"
            "WAIT_DONE_%=:\n\t}"
            :: "r"(bar), "r"(phase) : "memory");
    }
}

// ---------------------------------------------------------------------------
// Kernel A (fused): blocks [0, PROJ_BLOCKS): proj = h @ a, WARP-PER-2-ROWS
// register formulation (no smem, no __syncthreads). Each lane holds one
// float4 of each of the warp's two h rows; h scalars broadcast via shfl;
// `a` (64KB) streamed via LDG.128 and L1-resident after first touch.
// Blocks [PROJ_BLOCKS, ...): segment offsets from sorted segment_ids.
// ---------------------------------------------------------------------------
__global__ __launch_bounds__(256) void pre_kernel(const float* __restrict__ h,
                                                  const float* __restrict__ a,
                                                  const int* __restrict__ seg,
                                                  int n, int m) {
    int tid = threadIdx.x;

    if (blockIdx.x < PROJ_BLOCKS) {
        int lane = tid & 31;
        int w    = tid >> 5;
        int gw   = blockIdx.x * 8 + w;      // global warp id, 0..2047
        int r0   = gw * 2;
        int r1   = r0 + 1;

        const float4* h4 = (const float4*)h;
        const float4* a4 = (const float4*)a;

        float4 hA = h4[r0 * 32 + lane];     // lane holds h[r0][4l..4l+3]
        float4 hB = h4[r1 * 32 + lane];

        float4 accA = make_float4(0.f, 0.f, 0.f, 0.f);
        float4 accB = make_float4(0.f, 0.f, 0.f, 0.f);

#pragma unroll 4
        for (int k4 = 0; k4 < 32; k4++) {
            float ax = __shfl_sync(0xffffffffu, hA.x, k4);
            float ay = __shfl_sync(0xffffffffu, hA.y, k4);
            float az = __shfl_sync(0xffffffffu, hA.z, k4);
            float aw = __shfl_sync(0xffffffffu, hA.w, k4);
            float bx = __shfl_sync(0xffffffffu, hB.x, k4);
            float by = __shfl_sync(0xffffffffu, hB.y, k4);
            float bz = __shfl_sync(0xffffffffu, hB.z, k4);
            float bw = __shfl_sync(0xffffffffu, hB.w, k4);

            float4 av0 = a4[(k4 * 4 + 0) * 32 + lane];
            float4 av1 = a4[(k4 * 4 + 1) * 32 + lane];
            float4 av2 = a4[(k4 * 4 + 2) * 32 + lane];
            float4 av3 = a4[(k4 * 4 + 3) * 32 + lane];

            accA.x = fmaf(ax, av0.x, fmaf(ay, av1.x, fmaf(az, av2.x, fmaf(aw, av3.x, accA.x))));
            accA.y = fmaf(ax, av0.y, fmaf(ay, av1.y, fmaf(az, av2.y, fmaf(aw, av3.y, accA.y))));
            accA.z = fmaf(ax, av0.z, fmaf(ay, av1.z, fmaf(az, av2.z, fmaf(aw, av3.z, accA.z))));
            accA.w = fmaf(ax, av0.w, fmaf(ay, av1.w, fmaf(az, av2.w, fmaf(aw, av3.w, accA.w))));
            accB.x = fmaf(bx, av0.x, fmaf(by, av1.x, fmaf(bz, av2.x, fmaf(bw, av3.x, accB.x))));
            accB.y = fmaf(bx, av0.y, fmaf(by, av1.y, fmaf(bz, av2.y, fmaf(bw, av3.y, accB.y))));
            accB.z = fmaf(bx, av0.z, fmaf(by, av1.z, fmaf(bz, av2.z, fmaf(bw, av3.z, accB.z))));
            accB.w = fmaf(bx, av0.w, fmaf(by, av1.w, fmaf(bz, av2.w, fmaf(bw, av3.w, accB.w))));
        }

        float4* p4 = (float4*)g_proj;
        p4[r0 * 32 + lane] = accA;
        p4[r1 * 32 + lane] = accB;
    } else {
        // ---------------- segment offsets (int4 per thread) ----------------
        int t = (blockIdx.x - PROJ_BLOCKS) * 256 + tid;
        int base = t * 4;
        if (base >= n) return;
        int4 v = ((const int4*)seg)[t];
        int prev = (base == 0) ? -1 : __ldg(&seg[base - 1]);

        int ids[4] = {v.x, v.y, v.z, v.w};
#pragma unroll
        for (int k = 0; k < 4; k++) {
            int s = ids[k];
            for (int g = prev + 1; g <= s; ++g) g_offsets[g] = base + k;
            prev = s;
        }
        if (base + 4 >= n) {
            for (int g = prev + 1; g <= m; ++g) g_offsets[g] = n;
        }
    }
}

// ---------------------------------------------------------------------------
// Flash helpers
// ---------------------------------------------------------------------------
__device__ __forceinline__ float warp_dot(float4 v, float4 p) {
    float d = fmaf(v.x, p.x, fmaf(v.y, p.y, fmaf(v.z, p.z, v.w * p.w)));
    d += __shfl_xor_sync(0xffffffffu, d, 16);
    d += __shfl_xor_sync(0xffffffffu, d, 8);
    d += __shfl_xor_sync(0xffffffffu, d, 4);
    d += __shfl_xor_sync(0xffffffffu, d, 2);
    d += __shfl_xor_sync(0xffffffffu, d, 1);
    return d;
}

// 4-node flash update; nodes at b[0], b[32], b[64], b[96] (float4 units)
__device__ __forceinline__ void flash4(const float4* __restrict__ b, float4 p,
                                       float& m_w, float& z_w, float4& acc) {
    float4 v0 = b[0];
    float4 v1 = b[32];
    float4 v2 = b[64];
    float4 v3 = b[96];
    float d0 = warp_dot(v0, p);
    float d1 = warp_dot(v1, p);
    float d2 = warp_dot(v2, p);
    float d3 = warp_dot(v3, p);
    float m_new = fmaxf(fmaxf(m_w, fmaxf(d0, d1)), fmaxf(d2, d3));
    float c  = __expf(m_w - m_new);
    float e0 = __expf(d0 - m_new);
    float e1 = __expf(d1 - m_new);
    float e2 = __expf(d2 - m_new);
    float e3 = __expf(d3 - m_new);
    z_w   = fmaf(z_w, c, (e0 + e1) + (e2 + e3));
    acc.x = fmaf(acc.x, c, fmaf(e0, v0.x, fmaf(e1, v1.x, fmaf(e2, v2.x, e3 * v3.x))));
    acc.y = fmaf(acc.y, c, fmaf(e0, v0.y, fmaf(e1, v1.y, fmaf(e2, v2.y, e3 * v3.y))));
    acc.z = fmaf(acc.z, c, fmaf(e0, v0.z, fmaf(e1, v1.z, fmaf(e2, v2.z, e3 * v3.z))));
    acc.w = fmaf(acc.w, c, fmaf(e0, v0.w, fmaf(e1, v1.w, fmaf(e2, v2.w, e3 * v3.w))));
    m_w = m_new;
}

__device__ __forceinline__ void flash1(float4 v, float4 p,
                                       float& m_w, float& z_w, float4& acc) {
    float d  = warp_dot(v, p);
    float m_new = fmaxf(m_w, d);
    float c = __expf(m_w - m_new);
    float e = __expf(d - m_new);
    z_w   = fmaf(z_w, c, e);
    acc.x = fmaf(acc.x, c, e * v.x);
    acc.y = fmaf(acc.y, c, e * v.y);
    acc.z = fmaf(acc.z, c, e * v.z);
    acc.w = fmaf(acc.w, c, e * v.w);
    m_w = m_new;
}

// ---------------------------------------------------------------------------
// Kernel B: TWO WARPS PER GRAPH, bulk-async pipelined online softmax.
// (Round-5 version — best measured. 128-thread blocks; warps (2p, 2p+1)
// split graph p's contiguous node range; 8-node bulk chunks through a
// 2-stage smem ring; pair merged through smem.)
// ---------------------------------------------------------------------------
__global__ __launch_bounds__(128) void attn_kernel(const float* __restrict__ x,
                                                   float* __restrict__ out,
                                                   int m) {
    __shared__ float4   s_buf[4][STAGES][CHUNK * 32];  // 32 KB
    __shared__ uint64_t s_bar[4][STAGES];
    __shared__ float    s_m[4];
    __shared__ float    s_z[4];
    __shared__ float4   s_accs[2][32];

    int tid  = threadIdx.x;
    int lane = tid & 31;
    int w    = tid >> 5;    // 0..3
    int pp   = w >> 1;      // pair 0..1
    int half = w & 1;
    int g    = blockIdx.x * 2 + pp;

    if (lane == 0) {
        mbar_init(smem_u32(&s_bar[w][0]), 1);
        mbar_init(smem_u32(&s_bar[w][1]), 1);
    }
    __syncthreads();

    bool active = (g < m);
    int s0 = 0, e0 = 0;
    if (active) { s0 = g_offsets[g]; e0 = g_offsets[g + 1]; }
    int cnt = e0 - s0;
    int h0  = (cnt + 1) >> 1;
    int beg = half ? (s0 + h0) : s0;
    int fin = half ? e0 : (s0 + h0);
    int len = fin - beg;
    int nfull = len >> 3;            // full CHUNK-node chunks

    const float4* x4 = (const float4*)x;

    float4 p = make_float4(0.f, 0.f, 0.f, 0.f);
    if (active && cnt > 0)
        p = ((const float4*)g_proj)[g * 32 + lane];

    // ---- prologue: fill the pipeline ----
    if (lane == 0) {
        int npre = nfull < STAGES ? nfull : STAGES;
        for (int k = 0; k < npre; k++) {
            uint32_t bar = smem_u32(&s_bar[w][k]);
            mbar_expect(bar, CHUNK * 512u);
            bulk_ld(smem_u32(&s_buf[w][k][0]),
                    x4 + (size_t)(beg + k * CHUNK) * 32, CHUNK * 512u, bar);
        }
    }

    const float NEG_INF = -3.402823466e38f;
    float  m_w = NEG_INF;
    float  z_w = 0.f;
    float4 acc = make_float4(0.f, 0.f, 0.f, 0.f);

    // ---- main pipelined loop ----
    for (int c = 0; c < nfull; c++) {
        int st = c & 1;
        mbar_wait(smem_u32(&s_bar[w][st]), (c >> 1) & 1);
        const float4* b = &s_buf[w][st][lane];
        flash4(b,       p, m_w, z_w, acc);   // nodes 0..3
        flash4(b + 128, p, m_w, z_w, acc);   // nodes 4..7
        if (c + 2 < nfull && lane == 0) {
            uint32_t bar = smem_u32(&s_bar[w][st]);
            mbar_expect(bar, CHUNK * 512u);
            bulk_ld(smem_u32(&s_buf[w][st][0]),
                    x4 + (size_t)(beg + (c + 2) * CHUNK) * 32, CHUNK * 512u, bar);
        }
    }

    // ---- remainder nodes (<CHUNK) via direct LDG ----
    for (int i = beg + nfull * CHUNK; i < fin; ++i)
        flash1(x4[(size_t)i * 32 + lane], p, m_w, z_w, acc);

    // ---- pair combine ----
    if (lane == 0) { s_m[w] = m_w; s_z[w] = z_w; }
    if (half) s_accs[pp][lane] = acc;
    __syncthreads();

    if (!half && active) {
        float4* out4 = (float4*)out;
        if (cnt <= 0) {
            out4[g * 32 + lane] = make_float4(0.f, 0.f, 0.f, 0.f);
        } else {
            float  m1 = s_m[w + 1];
            float  z1 = s_z[w + 1];
            float4 a1 = s_accs[pp][lane];
            float mg = fmaxf(m_w, m1);       // finite: half0 non-empty
            float f0 = __expf(m_w - mg);
            float f1 = __expf(m1 - mg);      // 0 if half1 empty
            float z  = fmaf(z_w, f0, z1 * f1);
            float inv = 1.f / z;
            out4[g * 32 + lane] = make_float4(
                fmaf(acc.x, f0, a1.x * f1) * inv,
                fmaf(acc.y, f0, a1.y * f1) * inv,
                fmaf(acc.z, f0, a1.z * f1) * inv,
                fmaf(acc.w, f0, a1.w * f1) * inv);
        }
    }
}

// ---------------------------------------------------------------------------
// Launch: inputs per metadata order: h (M*128 f32), x (N*128 f32),
// a (128*128 f32), segment_ids (N int32). Output: M*128 f32.
// ---------------------------------------------------------------------------
extern "C" void kernel_launch(void* const* d_in, const int* in_sizes, int n_in,
                              void* d_out, int out_size) {
    const float* h   = (const float*)d_in[0];
    const float* x   = (const float*)d_in[1];
    const float* a   = (const float*)d_in[2];
    const int*   seg = (const int*)d_in[3];
    float* out = (float*)d_out;

    int m = in_sizes[0] / D;   // 4096
    int n = in_sizes[3];       // 262144

    int n4 = (n + 3) / 4;
    int off_blocks = (n4 + 255) / 256;
    pre_kernel<<<PROJ_BLOCKS + off_blocks, 256>>>(h, a, seg, n, m);
    attn_kernel<<<(m + 1) / 2, 128>>>(x, out, m);
}

// round 9
// speedup vs baseline: 1.1731x; 1.1319x over previous
#include <cuda_runtime.h>
#include <cstdint>

#define D 128            // DH == DX == 128
#define MAX_M 4096
#define MAX_N 262144

#define PROJ_BLOCKS 256      // 16 rows each -> 4096 rows
#define PROJ_ROWS   16

#define CHUNK  8             // nodes per bulk copy (8 * 512B = 4KB)
#define STAGES 3             // per-warp ring depth (12KB)
#define WINDOW 128           // nodes per ownership window (16 chunks)

// Scratch (no allocations allowed): proj matrix + segment offsets
__device__ float g_proj[MAX_M * D];
__device__ int   g_offsets[MAX_M + 1];

// ---------------------------------------------------------------------------
// PTX helpers: mbarrier + cp.async.bulk
// ---------------------------------------------------------------------------
__device__ __forceinline__ uint32_t smem_u32(const void* p) {
    return (uint32_t)__cvta_generic_to_shared(p);
}
__device__ __forceinline__ void mbar_init(uint32_t bar, uint32_t cnt) {
    asm volatile("mbarrier.init.shared.b64 [%0], %1;" :: "r"(bar), "r"(cnt) : "memory");
}
__device__ __forceinline__ void mbar_expect(uint32_t bar, uint32_t bytes) {
    asm volatile("mbarrier.arrive.expect_tx.shared.b64 _, [%0], %1;"
                 :: "r"(bar), "r"(bytes) : "memory");
}
__device__ __forceinline__ void bulk_ld(uint32_t dst, const void* src,
                                        uint32_t bytes, uint32_t bar) {
    asm volatile(
        "cp.async.bulk.shared::cta.global.mbarrier::complete_tx::bytes [%0], [%1], %2, [%3];"
        :: "r"(dst), "l"(src), "r"(bytes), "r"(bar) : "memory");
}
__device__ __forceinline__ void mbar_wait(uint32_t bar, uint32_t phase) {
    uint32_t done;
    asm volatile(
        "{\n\t.reg .pred p;\n\t"
        "mbarrier.try_wait.parity.acquire.cta.shared::cta.b64 p, [%1], %2;\n\t"
        "selp.b32 %0, 1, 0, p;\n\t}"
        : "=r"(done) : "r"(bar), "r"(phase) : "memory");
    if (!done) {
        asm volatile(
            "{\n\t.reg .pred P1;\n\t"
            "WAIT_LOOP_%=:\n\t"
            "mbarrier.try_wait.parity.acquire.cta.shared::cta.b64 P1, [%0], %1, 0x989680;\n\t"
            "@P1 bra.uni WAIT_DONE_%=;\n\t"
            "bra.uni WAIT_LOOP_%=;\n\t"
            "WAIT_DONE_%=:\n\t}"
            :: "r"(bar), "r"(phase) : "memory");
    }
}

// ---------------------------------------------------------------------------
// Kernel A (fused, ROUND-5 VERSION — best measured): proj = h @ a + offsets.
// ---------------------------------------------------------------------------
__global__ __launch_bounds__(256) void pre_kernel(const float* __restrict__ h,
                                                  const float* __restrict__ a,
                                                  const int* __restrict__ seg,
                                                  int n, int m) {
    __shared__ float a_sh[64 * D];          // 32 KB (one k-half of a)
    __shared__ float h_sh[PROJ_ROWS * D];   // 8 KB

    int tid = threadIdx.x;

    if (blockIdx.x < PROJ_BLOCKS) {
        int cg = tid & 31;
        int rg = tid >> 5;
        int rowBase = blockIdx.x * PROJ_ROWS;

        const float4* h4 = (const float4*)h;
        const float4* a4 = (const float4*)a;
        float4* h_sh4 = (float4*)h_sh;
        float4* a_sh4 = (float4*)a_sh;

        for (int idx = tid; idx < PROJ_ROWS * (D / 4); idx += 256)
            h_sh4[idx] = h4[rowBase * (D / 4) + idx];

        float acc[2][4];
#pragma unroll
        for (int r = 0; r < 2; r++)
            acc[r][0] = acc[r][1] = acc[r][2] = acc[r][3] = 0.f;

        for (int half = 0; half < 2; half++) {
            __syncthreads();
            for (int idx = tid; idx < 64 * (D / 4); idx += 256)
                a_sh4[idx] = a4[half * 64 * (D / 4) + idx];
            __syncthreads();

#pragma unroll 8
            for (int k2 = 0; k2 < 64; k2++) {
                float4 av = *(const float4*)&a_sh[k2 * D + cg * 4];
                int k = half * 64 + k2;
#pragma unroll
                for (int r = 0; r < 2; r++) {
                    float hv = h_sh[(rg * 2 + r) * D + k];
                    acc[r][0] = fmaf(hv, av.x, acc[r][0]);
                    acc[r][1] = fmaf(hv, av.y, acc[r][1]);
                    acc[r][2] = fmaf(hv, av.z, acc[r][2]);
                    acc[r][3] = fmaf(hv, av.w, acc[r][3]);
                }
            }
        }

        float4* p4 = (float4*)g_proj;
#pragma unroll
        for (int r = 0; r < 2; r++) {
            int row = rowBase + rg * 2 + r;
            p4[row * (D / 4) + cg] =
                make_float4(acc[r][0], acc[r][1], acc[r][2], acc[r][3]);
        }
    } else {
        int t = (blockIdx.x - PROJ_BLOCKS) * 256 + tid;
        int base = t * 4;
        if (base >= n) return;
        int4 v = ((const int4*)seg)[t];
        int prev = (base == 0) ? -1 : __ldg(&seg[base - 1]);

        int ids[4] = {v.x, v.y, v.z, v.w};
#pragma unroll
        for (int k = 0; k < 4; k++) {
            int s = ids[k];
            for (int g = prev + 1; g <= s; ++g) g_offsets[g] = base + k;
            prev = s;
        }
        if (base + 4 >= n) {
            for (int g = prev + 1; g <= m; ++g) g_offsets[g] = n;
        }
    }
}

// ---------------------------------------------------------------------------
// Flash helpers
// ---------------------------------------------------------------------------
__device__ __forceinline__ float warp_dot(float4 v, float4 p) {
    float d = fmaf(v.x, p.x, fmaf(v.y, p.y, fmaf(v.z, p.z, v.w * p.w)));
    d += __shfl_xor_sync(0xffffffffu, d, 16);
    d += __shfl_xor_sync(0xffffffffu, d, 8);
    d += __shfl_xor_sync(0xffffffffu, d, 4);
    d += __shfl_xor_sync(0xffffffffu, d, 2);
    d += __shfl_xor_sync(0xffffffffu, d, 1);
    return d;
}

__device__ __forceinline__ void flash4(const float4* __restrict__ b, float4 p,
                                       float& m_w, float& z_w, float4& acc) {
    float4 v0 = b[0];
    float4 v1 = b[32];
    float4 v2 = b[64];
    float4 v3 = b[96];
    float d0 = warp_dot(v0, p);
    float d1 = warp_dot(v1, p);
    float d2 = warp_dot(v2, p);
    float d3 = warp_dot(v3, p);
    float m_new = fmaxf(fmaxf(m_w, fmaxf(d0, d1)), fmaxf(d2, d3));
    float c  = __expf(m_w - m_new);
    float e0 = __expf(d0 - m_new);
    float e1 = __expf(d1 - m_new);
    float e2 = __expf(d2 - m_new);
    float e3 = __expf(d3 - m_new);
    z_w   = fmaf(z_w, c, (e0 + e1) + (e2 + e3));
    acc.x = fmaf(acc.x, c, fmaf(e0, v0.x, fmaf(e1, v1.x, fmaf(e2, v2.x, e3 * v3.x))));
    acc.y = fmaf(acc.y, c, fmaf(e0, v0.y, fmaf(e1, v1.y, fmaf(e2, v2.y, e3 * v3.y))));
    acc.z = fmaf(acc.z, c, fmaf(e0, v0.z, fmaf(e1, v1.z, fmaf(e2, v2.z, e3 * v3.z))));
    acc.w = fmaf(acc.w, c, fmaf(e0, v0.w, fmaf(e1, v1.w, fmaf(e2, v2.w, e3 * v3.w))));
    m_w = m_new;
}

__device__ __forceinline__ void flash1(float4 v, float4 p,
                                       float& m_w, float& z_w, float4& acc) {
    float d  = warp_dot(v, p);
    float m_new = fmaxf(m_w, d);
    float c = __expf(m_w - m_new);
    float e = __expf(d - m_new);
    z_w   = fmaf(z_w, c, e);
    acc.x = fmaf(acc.x, c, e * v.x);
    acc.y = fmaf(acc.y, c, e * v.y);
    acc.z = fmaf(acc.z, c, e * v.z);
    acc.w = fmaf(acc.w, c, e * v.w);
    m_w = m_new;
}

// ---------------------------------------------------------------------------
// Kernel B: GRAPH-ALIGNED WINDOW streaming online softmax.
// Warp w owns every graph whose START node lies in [w*WINDOW, (w+1)*WINDOW).
// Its node span = union of those graphs (contiguous, ~WINDOW nodes, may spill
// past the window end). The span streams through a STAGES-deep bulk-async
// ring CONTINUOUSLY — one pipeline fill per ~16 chunks instead of per graph.
// Graph boundaries handled in the consumer; every owned graph written
// directly (empty -> zeros). No scratch, no combine pass.
// ---------------------------------------------------------------------------
__global__ __launch_bounds__(128) void attn_kernel(const float* __restrict__ x,
                                                   const int* __restrict__ seg,
                                                   float* __restrict__ out,
                                                   int n, int m) {
    extern __shared__ unsigned char dyn[];
    float4*   bufs = (float4*)dyn;                            // [4][STAGES][CHUNK*32]
    uint64_t* bars = (uint64_t*)(dyn + 4 * STAGES * CHUNK * 512);

    int tid  = threadIdx.x;
    int lane = tid & 31;
    int w    = tid >> 5;

    float4*   buf = bufs + w * STAGES * (CHUNK * 32);
    uint64_t* bar = bars + w * STAGES;

    if (lane == 0)
        for (int s = 0; s < STAGES; s++) mbar_init(smem_u32(&bar[s]), 1);
    __syncthreads();

    int wid   = blockIdx.x * 4 + w;
    int nodeA = wid * WINDOW;
    if (nodeA >= n) return;
    int nodeB = nodeA + WINDOW < n ? nodeA + WINDOW : n;

    // ---- ownership: graphs starting in [nodeA, nodeB) ----
    int gF, gL;
    {
        int gC = __ldg(&seg[nodeA]);                 // graph containing nodeA
        if (g_offsets[gC] >= nodeA) {                // == nodeA
            gF = gC;
            while (gF > 0 && g_offsets[gF - 1] >= nodeA) gF--;
        } else {
            gF = gC + 1;
        }
        if (nodeB >= n) {
            gL = m - 1;                              // last window owns the rest
        } else {
            int gD = __ldg(&seg[nodeB]);
            if (g_offsets[gD] >= nodeB) {            // == nodeB
                gL = gD - 1;
                while (gL >= 0 && g_offsets[gL] >= nodeB) gL--;
            } else {
                gL = gD;
            }
        }
    }
    if (gF > gL) return;                             // no graph starts here

    float4* out4 = (float4*)out;
    int S = g_offsets[gF];
    int E = g_offsets[gL + 1];
    if (S >= E) {                                    // all owned graphs empty
        for (int g = gF; g <= gL; g++)
            out4[g * 32 + lane] = make_float4(0.f, 0.f, 0.f, 0.f);
        return;
    }
    int len = E - S;
    int nch = (len + CHUNK - 1) / CHUNK;

    const float4* x4 = (const float4*)x;

    // ---- prologue: fill the ring ----
    if (lane == 0) {
        int npre = nch < STAGES ? nch : STAGES;
        for (int k = 0; k < npre; k++) {
            int remn = len - k * CHUNK;
            uint32_t bytes = (uint32_t)(remn < CHUNK ? remn : CHUNK) * 512u;
            uint32_t b = smem_u32(&bar[k]);
            mbar_expect(b, bytes);
            bulk_ld(smem_u32(buf + k * (CHUNK * 32)),
                    x4 + (size_t)(S + k * CHUNK) * 32, bytes, b);
        }
    }

    // ---- segment state (zero leading empties at S) ----
    int g = gF;
    while (g_offsets[g + 1] <= S) {
        out4[g * 32 + lane] = make_float4(0.f, 0.f, 0.f, 0.f);
        g++;
    }
    int eg = g_offsets[g + 1];
    const float4* pr4 = (const float4*)g_proj;
    float4 p = pr4[g * 32 + lane];

    const float NEG_INF = -3.402823466e38f;
    float  mw  = NEG_INF;
    float  zw  = 0.f;
    float4 acc = make_float4(0.f, 0.f, 0.f, 0.f);

    // ---- continuous chunk stream ----
    int st = 0, ph = 0;
    for (int c = 0; c < nch; c++) {
        mbar_wait(smem_u32(&bar[st]), ph);
        const float4* bs = buf + st * (CHUNK * 32);
        int cbeg = S + c * CHUNK;
        int cend = cbeg + CHUNK < E ? cbeg + CHUNK : E;

        int i = cbeg;
        while (i < cend) {
            if (i >= eg) {
                // close current graph
                float inv = 1.f / zw;
                out4[g * 32 + lane] =
                    make_float4(acc.x * inv, acc.y * inv, acc.z * inv, acc.w * inv);
                g++;
                while (g_offsets[g + 1] <= i) {      // skipped graphs are empty
                    out4[g * 32 + lane] = make_float4(0.f, 0.f, 0.f, 0.f);
                    g++;
                }
                eg = g_offsets[g + 1];
                p  = pr4[g * 32 + lane];
                mw = NEG_INF; zw = 0.f;
                acc = make_float4(0.f, 0.f, 0.f, 0.f);
            }
            int stop = cend < eg ? cend : eg;
            const float4* bp = bs + (i - cbeg) * 32 + lane;
            while (stop - i >= 4) { flash4(bp, p, mw, zw, acc); bp += 128; i += 4; }
            while (i < stop)      { flash1(*bp, p, mw, zw, acc); bp += 32;  i += 1; }
        }

        __syncwarp();
        if (lane == 0 && c + STAGES < nch) {
            int k = c + STAGES;
            int remn = len - k * CHUNK;
            uint32_t bytes = (uint32_t)(remn < CHUNK ? remn : CHUNK) * 512u;
            uint32_t b = smem_u32(&bar[st]);
            mbar_expect(b, bytes);
            bulk_ld(smem_u32(buf + st * (CHUNK * 32)),
                    x4 + (size_t)(S + k * CHUNK) * 32, bytes, b);
        }
        st++; if (st == STAGES) { st = 0; ph ^= 1; }
    }

    // ---- final close (last graph ends exactly at E) ----
    {
        float inv = 1.f / zw;
        out4[g * 32 + lane] =
            make_float4(acc.x * inv, acc.y * inv, acc.z * inv, acc.w * inv);
    }
    // trailing empties (possible in the last window)
    for (int gg = g + 1; gg <= gL; gg++)
        out4[gg * 32 + lane] = make_float4(0.f, 0.f, 0.f, 0.f);
}

// ---------------------------------------------------------------------------
// Launch: inputs per metadata order: h (M*128 f32), x (N*128 f32),
// a (128*128 f32), segment_ids (N int32). Output: M*128 f32.
// ---------------------------------------------------------------------------
extern "C" void kernel_launch(void* const* d_in, const int* in_sizes, int n_in,
                              void* d_out, int out_size) {
    const float* h   = (const float*)d_in[0];
    const float* x   = (const float*)d_in[1];
    const float* a   = (const float*)d_in[2];
    const int*   seg = (const int*)d_in[3];
    float* out = (float*)d_out;

    int m = in_sizes[0] / D;   // 4096
    int n = in_sizes[3];       // 262144

    int n4 = (n + 3) / 4;
    int off_blocks = (n4 + 255) / 256;
    pre_kernel<<<PROJ_BLOCKS + off_blocks, 256>>>(h, a, seg, n, m);

    int smem_bytes = 4 * STAGES * CHUNK * 512 + 4 * STAGES * 8;   // 49248
    static bool attr_set = false;
    if (!attr_set) {
        cudaFuncSetAttribute(attn_kernel,
                             cudaFuncAttributeMaxDynamicSharedMemorySize,
                             smem_bytes);
        attr_set = true;
    }
    int windows = (n + WINDOW - 1) / WINDOW;
    int ablocks = (windows + 3) / 4;
    attn_kernel<<<ablocks, 128, smem_bytes>>>(x, seg, out, n, m);
}

// round 10
// speedup vs baseline: 1.1739x; 1.0007x over previous
#include <cuda_runtime.h>
#include <cstdint>

#define D 128            // DH == DX == 128

#define CHUNK  8             // nodes per bulk copy (8 * 512B = 4KB)
#define STAGES 3             // per-warp ring depth (12KB)
#define WINDOW 128           // nodes per ownership window (16 chunks)
#define GRID   512           // MUST be <= resident capacity (4/SM x 148 = 592)
#define THREADS 128

#define MAX_M 4096
#define MAX_N 262144

// Scratch (no allocations allowed)
__device__ float    g_proj[MAX_M * D];
__device__ int      g_offsets[MAX_M + 1];
__device__ unsigned g_arrive;   // monotonic epoch counter (never reset)

// ---------------------------------------------------------------------------
// PTX helpers: mbarrier + cp.async.bulk
// ---------------------------------------------------------------------------
__device__ __forceinline__ uint32_t smem_u32(const void* p) {
    return (uint32_t)__cvta_generic_to_shared(p);
}
__device__ __forceinline__ void mbar_init(uint32_t bar, uint32_t cnt) {
    asm volatile("mbarrier.init.shared.b64 [%0], %1;" :: "r"(bar), "r"(cnt) : "memory");
}
__device__ __forceinline__ void mbar_expect(uint32_t bar, uint32_t bytes) {
    asm volatile("mbarrier.arrive.expect_tx.shared.b64 _, [%0], %1;"
                 :: "r"(bar), "r"(bytes) : "memory");
}
__device__ __forceinline__ void bulk_ld(uint32_t dst, const void* src,
                                        uint32_t bytes, uint32_t bar) {
    asm volatile(
        "cp.async.bulk.shared::cta.global.mbarrier::complete_tx::bytes [%0], [%1], %2, [%3];"
        :: "r"(dst), "l"(src), "r"(bytes), "r"(bar) : "memory");
}
__device__ __forceinline__ void mbar_wait(uint32_t bar, uint32_t phase) {
    uint32_t done;
    asm volatile(
        "{\n\t.reg .pred p;\n\t"
        "mbarrier.try_wait.parity.acquire.cta.shared::cta.b64 p, [%1], %2;\n\t"
        "selp.b32 %0, 1, 0, p;\n\t}"
        : "=r"(done) : "r"(bar), "r"(phase) : "memory");
    if (!done) {
        asm volatile(
            "{\n\t.reg .pred P1;\n\t"
            "WAIT_LOOP_%=:\n\t"
            "mbarrier.try_wait.parity.acquire.cta.shared::cta.b64 P1, [%0], %1, 0x989680;\n\t"
            "@P1 bra.uni WAIT_DONE_%=;\n\t"
            "bra.uni WAIT_LOOP_%=;\n\t"
            "WAIT_DONE_%=:\n\t}"
            :: "r"(bar), "r"(phase) : "memory");
    }
}

// ---------------------------------------------------------------------------
// Flash helpers
// ---------------------------------------------------------------------------
__device__ __forceinline__ float warp_dot(float4 v, float4 p) {
    float d = fmaf(v.x, p.x, fmaf(v.y, p.y, fmaf(v.z, p.z, v.w * p.w)));
    d += __shfl_xor_sync(0xffffffffu, d, 16);
    d += __shfl_xor_sync(0xffffffffu, d, 8);
    d += __shfl_xor_sync(0xffffffffu, d, 4);
    d += __shfl_xor_sync(0xffffffffu, d, 2);
    d += __shfl_xor_sync(0xffffffffu, d, 1);
    return d;
}

__device__ __forceinline__ void flash4(const float4* __restrict__ b, float4 p,
                                       float& m_w, float& z_w, float4& acc) {
    float4 v0 = b[0];
    float4 v1 = b[32];
    float4 v2 = b[64];
    float4 v3 = b[96];
    float d0 = warp_dot(v0, p);
    float d1 = warp_dot(v1, p);
    float d2 = warp_dot(v2, p);
    float d3 = warp_dot(v3, p);
    float m_new = fmaxf(fmaxf(m_w, fmaxf(d0, d1)), fmaxf(d2, d3));
    float c  = __expf(m_w - m_new);
    float e0 = __expf(d0 - m_new);
    float e1 = __expf(d1 - m_new);
    float e2 = __expf(d2 - m_new);
    float e3 = __expf(d3 - m_new);
    z_w   = fmaf(z_w, c, (e0 + e1) + (e2 + e3));
    acc.x = fmaf(acc.x, c, fmaf(e0, v0.x, fmaf(e1, v1.x, fmaf(e2, v2.x, e3 * v3.x))));
    acc.y = fmaf(acc.y, c, fmaf(e0, v0.y, fmaf(e1, v1.y, fmaf(e2, v2.y, e3 * v3.y))));
    acc.z = fmaf(acc.z, c, fmaf(e0, v0.z, fmaf(e1, v1.z, fmaf(e2, v2.z, e3 * v3.z))));
    acc.w = fmaf(acc.w, c, fmaf(e0, v0.w, fmaf(e1, v1.w, fmaf(e2, v2.w, e3 * v3.w))));
    m_w = m_new;
}

__device__ __forceinline__ void flash1(float4 v, float4 p,
                                       float& m_w, float& z_w, float4& acc) {
    float d  = warp_dot(v, p);
    float m_new = fmaxf(m_w, d);
    float c = __expf(m_w - m_new);
    float e = __expf(d - m_new);
    z_w   = fmaf(z_w, c, e);
    acc.x = fmaf(acc.x, c, e * v.x);
    acc.y = fmaf(acc.y, c, e * v.y);
    acc.z = fmaf(acc.z, c, e * v.z);
    acc.w = fmaf(acc.w, c, e * v.w);
    m_w = m_new;
}

// ---------------------------------------------------------------------------
// FUSED kernel: phase 1 (offsets + proj) -> device barrier -> phase 2 (attn).
// Grid = 512 co-resident blocks; barrier is a monotonic epoch counter, safe
// across graph replays without reset. Phase-1 proj stages `a` in the ring
// smem region (overlay); phase-2 re-uses it as the bulk-async ring.
// ---------------------------------------------------------------------------
__global__ __launch_bounds__(THREADS, 4)
void fused_kernel(const float* __restrict__ h,
                  const float* __restrict__ a,
                  const float* __restrict__ x,
                  const int*   __restrict__ seg,
                  float* __restrict__ out,
                  int n, int m) {
    extern __shared__ unsigned char dyn[];   // 48KB: phase1 overlay + phase2 ring
    __shared__ uint64_t s_bar[4][STAGES];

    int tid  = threadIdx.x;
    int lane = tid & 31;
    int w    = tid >> 5;

    // ======================= PHASE 1a: segment offsets =======================
    {
        int nt4 = (n + 3) >> 2;
        for (int t = blockIdx.x * THREADS + tid; t < nt4;
             t += gridDim.x * THREADS) {
            int base = t * 4;
            int4 v = ((const int4*)seg)[t];
            int prev = (base == 0) ? -1 : __ldg(&seg[base - 1]);
            int ids[4] = {v.x, v.y, v.z, v.w};
#pragma unroll
            for (int k = 0; k < 4; k++) {
                int s = ids[k];
                for (int g = prev + 1; g <= s; ++g) g_offsets[g] = base + k;
                prev = s;
            }
            if (base + 4 >= n) {
                for (int g = prev + 1; g <= m; ++g) g_offsets[g] = n;
            }
        }
    }

    // ======================= PHASE 1b: proj = h @ a =========================
    {
        float* a_sh = (float*)dyn;                 // 32KB: one k-half of a
        float* h_sh = (float*)(dyn + 32768);       // 4KB:  8 h rows

        int cg = lane;             // column group: 4 cols at cg*4
        int rg = w;                // warp handles rows rg*2, rg*2+1

        const float4* h4 = (const float4*)h;
        const float4* a4 = (const float4*)a;
        float4* hsh4 = (float4*)h_sh;
        float4* ash4 = (float4*)a_sh;

        for (int rb = blockIdx.x * 8; rb < m; rb += gridDim.x * 8) {
            for (int i = tid; i < 8 * 32; i += THREADS) {
                int gi = rb * 32 + i;
                if (gi < m * 32) hsh4[i] = h4[gi];
            }

            float acc[2][4];
#pragma unroll
            for (int r = 0; r < 2; r++)
                acc[r][0] = acc[r][1] = acc[r][2] = acc[r][3] = 0.f;

            for (int half = 0; half < 2; half++) {
                __syncthreads();
                for (int i = tid; i < 64 * 32; i += THREADS)
                    ash4[i] = a4[half * 64 * 32 + i];
                __syncthreads();

#pragma unroll 8
                for (int k2 = 0; k2 < 64; k2++) {
                    float4 av = ash4[k2 * 32 + cg];
                    int k = half * 64 + k2;
#pragma unroll
                    for (int r = 0; r < 2; r++) {
                        float hv = h_sh[(rg * 2 + r) * D + k];
                        acc[r][0] = fmaf(hv, av.x, acc[r][0]);
                        acc[r][1] = fmaf(hv, av.y, acc[r][1]);
                        acc[r][2] = fmaf(hv, av.z, acc[r][2]);
                        acc[r][3] = fmaf(hv, av.w, acc[r][3]);
                    }
                }
            }

            float4* p4 = (float4*)g_proj;
#pragma unroll
            for (int r = 0; r < 2; r++) {
                int row = rb + rg * 2 + r;
                if (row < m)
                    p4[row * 32 + cg] =
                        make_float4(acc[r][0], acc[r][1], acc[r][2], acc[r][3]);
            }
            __syncthreads();   // protect h_sh before next strided tile
        }
    }

    // ======================= DEVICE-WIDE BARRIER ============================
    __syncthreads();
    if (tid == 0) {
        __threadfence();
        unsigned t0 = atomicAdd(&g_arrive, 1u);
        unsigned target = (t0 / gridDim.x + 1u) * gridDim.x;
        while (atomicAdd(&g_arrive, 0u) < target) __nanosleep(128);
        __threadfence();
    }
    __syncthreads();

    // ======================= PHASE 2: window-streaming attn =================
    float4*   bufs = (float4*)dyn;   // [4][STAGES][CHUNK*32]
    float4*   buf  = bufs + w * STAGES * (CHUNK * 32);

    if (lane == 0)
        for (int s = 0; s < STAGES; s++) mbar_init(smem_u32(&s_bar[w][s]), 1);
    __syncthreads();

    const float4* x4   = (const float4*)x;
    const float4* pr4  = (const float4*)g_proj;
    float4*       out4 = (float4*)out;
    const float NEG_INF = -3.402823466e38f;

    unsigned cc = 0;   // global chunk counter: carries ring stage + parity
    int windows = (n + WINDOW - 1) / WINDOW;

    for (int wid = blockIdx.x * 4 + w; wid < windows; wid += gridDim.x * 4) {
        __syncwarp();
        int nodeA = wid * WINDOW;
        int nodeB = nodeA + WINDOW < n ? nodeA + WINDOW : n;

        // ---- ownership: graphs starting in [nodeA, nodeB) ----
        int gF, gL;
        {
            int gC = __ldg(&seg[nodeA]);
            if (g_offsets[gC] >= nodeA) {
                gF = gC;
                while (gF > 0 && g_offsets[gF - 1] >= nodeA) gF--;
            } else {
                gF = gC + 1;
            }
            if (nodeB >= n) {
                gL = m - 1;
            } else {
                int gD = __ldg(&seg[nodeB]);
                if (g_offsets[gD] >= nodeB) {
                    gL = gD - 1;
                    while (gL >= 0 && g_offsets[gL] >= nodeB) gL--;
                } else {
                    gL = gD;
                }
            }
        }
        if (gF > gL) continue;

        int S = g_offsets[gF];
        int E = g_offsets[gL + 1];
        if (S >= E) {                          // all owned graphs empty
            for (int g = gF; g <= gL; g++)
                out4[g * 32 + lane] = make_float4(0.f, 0.f, 0.f, 0.f);
            continue;
        }
        int len = E - S;
        int nch = (len + CHUNK - 1) / CHUNK;

        // ---- prologue: fill the ring ----
        if (lane == 0) {
            int npre = nch < STAGES ? nch : STAGES;
            for (int k = 0; k < npre; k++) {
                unsigned q = cc + k;
                int st = q % STAGES;
                int remn = len - k * CHUNK;
                uint32_t bytes = (uint32_t)(remn < CHUNK ? remn : CHUNK) * 512u;
                uint32_t b = smem_u32(&s_bar[w][st]);
                mbar_expect(b, bytes);
                bulk_ld(smem_u32(buf + st * (CHUNK * 32)),
                        x4 + (size_t)(S + k * CHUNK) * 32, bytes, b);
            }
        }

        // ---- segment state (zero leading empties at S) ----
        int g = gF;
        while (g_offsets[g + 1] <= S) {
            out4[g * 32 + lane] = make_float4(0.f, 0.f, 0.f, 0.f);
            g++;
        }
        int eg = g_offsets[g + 1];
        float4 p = pr4[g * 32 + lane];

        float  mw  = NEG_INF;
        float  zw  = 0.f;
        float4 acc = make_float4(0.f, 0.f, 0.f, 0.f);

        // ---- continuous chunk stream ----
        for (int c = 0; c < nch; c++) {
            unsigned q = cc + c;
            int st = q % STAGES;
            int ph = (q / STAGES) & 1;
            mbar_wait(smem_u32(&s_bar[w][st]), ph);
            const float4* bs = buf + st * (CHUNK * 32);
            int cbeg = S + c * CHUNK;
            int cend = cbeg + CHUNK < E ? cbeg + CHUNK : E;

            int i = cbeg;
            while (i < cend) {
                if (i >= eg) {
                    float inv = 1.f / zw;
                    out4[g * 32 + lane] =
                        make_float4(acc.x * inv, acc.y * inv, acc.z * inv, acc.w * inv);
                    g++;
                    while (g_offsets[g + 1] <= i) {
                        out4[g * 32 + lane] = make_float4(0.f, 0.f, 0.f, 0.f);
                        g++;
                    }
                    eg = g_offsets[g + 1];
                    p  = pr4[g * 32 + lane];
                    mw = NEG_INF; zw = 0.f;
                    acc = make_float4(0.f, 0.f, 0.f, 0.f);
                }
                int stop = cend < eg ? cend : eg;
                const float4* bp = bs + (i - cbeg) * 32 + lane;
                while (stop - i >= 4) { flash4(bp, p, mw, zw, acc); bp += 128; i += 4; }
                while (i < stop)      { flash1(*bp, p, mw, zw, acc); bp += 32;  i += 1; }
            }

            __syncwarp();
            if (lane == 0 && c + STAGES < nch) {
                int k = c + STAGES;
                int remn = len - k * CHUNK;
                uint32_t bytes = (uint32_t)(remn < CHUNK ? remn : CHUNK) * 512u;
                uint32_t b = smem_u32(&s_bar[w][st]);
                mbar_expect(b, bytes);
                bulk_ld(smem_u32(buf + st * (CHUNK * 32)),
                        x4 + (size_t)(S + k * CHUNK) * 32, bytes, b);
            }
        }
        cc += nch;

        // ---- final close + trailing empties ----
        {
            float inv = 1.f / zw;
            out4[g * 32 + lane] =
                make_float4(acc.x * inv, acc.y * inv, acc.z * inv, acc.w * inv);
        }
        for (int gg = g + 1; gg <= gL; gg++)
            out4[gg * 32 + lane] = make_float4(0.f, 0.f, 0.f, 0.f);
    }
}

// ---------------------------------------------------------------------------
// Launch: inputs per metadata order: h (M*128 f32), x (N*128 f32),
// a (128*128 f32), segment_ids (N int32). Output: M*128 f32.
// ---------------------------------------------------------------------------
extern "C" void kernel_launch(void* const* d_in, const int* in_sizes, int n_in,
                              void* d_out, int out_size) {
    const float* h   = (const float*)d_in[0];
    const float* x   = (const float*)d_in[1];
    const float* a   = (const float*)d_in[2];
    const int*   seg = (const int*)d_in[3];
    float* out = (float*)d_out;

    int m = in_sizes[0] / D;   // 4096
    int n = in_sizes[3];       // 262144

    int smem_bytes = 4 * STAGES * CHUNK * 512;   // 49152
    static bool attr_set = false;
    if (!attr_set) {
        cudaFuncSetAttribute(fused_kernel,
                             cudaFuncAttributeMaxDynamicSharedMemorySize,
                             smem_bytes);
        attr_set = true;
    }
    fused_kernel<<<GRID, THREADS, smem_bytes>>>(h, a, x, seg, out, n, m);
}